// round 15
// baseline (speedup 1.0000x reference)
#include <cuda_runtime.h>
#include <cuda_bf16.h>
#include <cstdint>

constexpr int Bb = 16, Ss = 64, Nn = 2048, Ee = 256;
constexpr int KS3 = 12;    // k-ranges for recurrence MMA
constexpr int NPB = 288;   // persistent blocks (3 gates x 8 nblk x 12 ks) = 144*2

// ---------------- scratch ----------------
__device__ uint16_t g_Eh[(size_t)Bb * Nn * Nn];
__device__ uint16_t g_El[(size_t)Bb * Nn * Nn];
__device__ float g_cs[Bb * Nn];
__device__ float g_AGG[Ss * Bb * Nn];
__device__ float g_part[3 * KS3 * Bb * Nn];
__device__ float g_h[Bb * Nn];
__device__ uint16_t g_Qh[(size_t)Bb * Nn * Ee];
__device__ uint16_t g_Ql[(size_t)Bb * Nn * Ee];
__device__ uint16_t g_Kh[(size_t)Bb * Nn * Ee];
__device__ uint16_t g_Kl[(size_t)Bb * Nn * Ee];
// W gate weights, fragment order, hi/lo interleaved per lane:
// [gate][ntile(256)][kstep(128)][lane(32)] -> uint4 {hi_reg0, hi_reg1, lo_reg0, lo_reg1}
__device__ uint4 g_WF4[3u * 256 * 128 * 32];
__device__ __nv_bfloat16 g_hh[Bb * Nn];
__device__ __nv_bfloat16 g_hl[Bb * Nn];
__device__ unsigned g_barcnt;

__device__ __forceinline__ void bf16split(float f, uint16_t& h, uint16_t& l) {
    __nv_bfloat16 hb = __float2bfloat16(f);
    __nv_bfloat16 lb = __float2bfloat16(f - __bfloat162float(hb));
    h = *(uint16_t*)&hb; l = *(uint16_t*)&lb;
}
__device__ __forceinline__ void mma16816(float* c, const uint32_t* a, const uint32_t* bfr) {
    asm volatile(
        "mma.sync.aligned.m16n8k16.row.col.f32.bf16.bf16.f32 "
        "{%0,%1,%2,%3}, {%4,%5,%6,%7}, {%8,%9}, {%0,%1,%2,%3};"
        : "+f"(c[0]), "+f"(c[1]), "+f"(c[2]), "+f"(c[3])
        : "r"(a[0]), "r"(a[1]), "r"(a[2]), "r"(a[3]), "r"(bfr[0]), "r"(bfr[1]));
}
__device__ __forceinline__ uint32_t smem_u32(const void* p) {
    uint32_t a;
    asm("{ .reg .u64 t; cvta.to.shared.u64 t, %1; cvt.u32.u64 %0, t; }" : "=r"(a) : "l"(p));
    return a;
}
__device__ __forceinline__ void ldsm4(uint32_t* d, uint32_t addr) {
    asm volatile("ldmatrix.sync.aligned.m8n8.x4.shared.b16 {%0,%1,%2,%3}, [%4];"
        : "=r"(d[0]), "=r"(d[1]), "=r"(d[2]), "=r"(d[3]) : "r"(addr));
}
__device__ __forceinline__ void cpasync16(uint32_t smem_dst, const void* gsrc) {
    asm volatile("cp.async.cg.shared.global [%0], [%1], 16;" :: "r"(smem_dst), "l"(gsrc));
}

// ======== Fused setup kernel: [0,1024)=k1 proj, [1024,1152)=zero, [1152,+12288)=W split ========
constexpr int A_K1 = 1024, A_Z = A_K1 + 128, A_W = A_Z + 12288;

__global__ __launch_bounds__(256) void kA(
    const float* __restrict__ x,
    const float* __restrict__ Wq, const float* __restrict__ bq,
    const float* __restrict__ Wk, const float* __restrict__ bk,
    const float* __restrict__ Whr, const float* __restrict__ Whz,
    const float* __restrict__ Whn)
{
    int bid = blockIdx.x;
    int tid = threadIdx.x;

    if (bid >= A_Z) {
        long long t = (long long)(bid - A_Z) * 256 + tid;
        int gate = (int)(t / (Nn * 512));
        int rem  = (int)(t % (Nn * 512));
        int n = rem / 512;
        int s = rem % 512;
        int kstep = s >> 2, q = s & 3;
        int k0 = kstep * 16 + q * 2;
        const float* W = (gate == 0) ? Whr : ((gate == 1) ? Whz : Whn);
        float w0 = W[(size_t)n * Nn + k0];
        float w1 = W[(size_t)n * Nn + k0 + 1];
        float w2 = W[(size_t)n * Nn + k0 + 8];
        float w3 = W[(size_t)n * Nn + k0 + 9];
        uint16_t h0, l0, h1, l1, h2, l2, h3, l3;
        bf16split(w0, h0, l0); bf16split(w1, h1, l1);
        bf16split(w2, h2, l2); bf16split(w3, h3, l3);
        uint4 v;
        v.x = (uint32_t)h0 | ((uint32_t)h1 << 16);
        v.y = (uint32_t)h2 | ((uint32_t)h3 << 16);
        v.z = (uint32_t)l0 | ((uint32_t)l1 << 16);
        v.w = (uint32_t)l2 | ((uint32_t)l3 << 16);
        int lane = (n & 7) * 4 + q;
        uint32_t idx = (((uint32_t)gate * 256 + (n >> 3)) * 128 + kstep) * 32 + lane;
        g_WF4[idx] = v;
        return;
    }
    if (bid >= A_K1) {
        int idx = (bid - A_K1) * 256 + tid;
        if (idx == 0) g_barcnt = 0u;
        if (idx < Bb * Nn) {
            g_cs[idx] = 0.f; g_h[idx] = 0.f;
            g_hh[idx] = __float2bfloat16(0.f);
            g_hl[idx] = __float2bfloat16(0.f);
        }
        return;
    }

    // ---- Q,K projection -> bf16 hi/lo ----
    __shared__ float As[16][132];
    __shared__ float wqs[64][16];
    __shared__ float wks[64][16];
    int bx = bid & 15, by = (bid >> 4) & 3, bz = bid >> 6;
    int b = bz, nbase = bx * 128, ebase = by * 64;
    int tn = tid % 16, te = tid / 16;

    float4 accq[8], acck[8];
    #pragma unroll
    for (int i = 0; i < 8; ++i) { accq[i] = make_float4(0,0,0,0); acck[i] = make_float4(0,0,0,0); }

    for (int kc = 0; kc < 4; ++kc) {
        int kbase = kc * 16;
        #pragma unroll
        for (int p = 0; p < 2; ++p) {
            int v = tid + 256 * p;
            int k = v / 32, mq = v % 32;
            *(float4*)&As[k][mq * 4] =
                *(const float4*)&x[((size_t)(b * Ss + kbase + k)) * Nn + nbase + mq * 4];
        }
        {
            int e = tid / 4, kq = tid % 4;
            *(float4*)&wqs[e][kq * 4] = *(const float4*)&Wq[(ebase + e) * Ss + kbase + kq * 4];
            *(float4*)&wks[e][kq * 4] = *(const float4*)&Wk[(ebase + e) * Ss + kbase + kq * 4];
        }
        __syncthreads();
        #pragma unroll
        for (int kk = 0; kk < 16; ++kk) {
            float4 alo = *(float4*)&As[kk][tn * 8];
            float4 ahi = *(float4*)&As[kk][tn * 8 + 4];
            float av[8] = {alo.x, alo.y, alo.z, alo.w, ahi.x, ahi.y, ahi.z, ahi.w};
            float wq0 = wqs[te*4+0][kk], wq1 = wqs[te*4+1][kk];
            float wq2 = wqs[te*4+2][kk], wq3 = wqs[te*4+3][kk];
            float wk0 = wks[te*4+0][kk], wk1 = wks[te*4+1][kk];
            float wk2 = wks[te*4+2][kk], wk3 = wks[te*4+3][kk];
            #pragma unroll
            for (int i = 0; i < 8; ++i) {
                accq[i].x += av[i]*wq0; accq[i].y += av[i]*wq1;
                accq[i].z += av[i]*wq2; accq[i].w += av[i]*wq3;
                acck[i].x += av[i]*wk0; acck[i].y += av[i]*wk1;
                acck[i].z += av[i]*wk2; acck[i].w += av[i]*wk3;
            }
        }
        __syncthreads();
    }
    float4 bq4 = *(const float4*)&bq[ebase + te * 4];
    float4 bk4 = *(const float4*)&bk[ebase + te * 4];
    #pragma unroll
    for (int i = 0; i < 8; ++i) {
        int n = nbase + tn * 8 + i;
        size_t o = ((size_t)b * Nn + n) * Ee + ebase + te * 4;
        float qa[4] = {accq[i].x + bq4.x, accq[i].y + bq4.y, accq[i].z + bq4.z, accq[i].w + bq4.w};
        float ka[4] = {acck[i].x + bk4.x, acck[i].y + bk4.y, acck[i].z + bk4.z, acck[i].w + bk4.w};
        ushort4 qh, ql, kh, kl;
        bf16split(qa[0], qh.x, ql.x); bf16split(qa[1], qh.y, ql.y);
        bf16split(qa[2], qh.z, ql.z); bf16split(qa[3], qh.w, ql.w);
        bf16split(ka[0], kh.x, kl.x); bf16split(ka[1], kh.y, kl.y);
        bf16split(ka[2], kh.z, kl.z); bf16split(ka[3], kh.w, kl.w);
        *(ushort4*)&g_Qh[o] = qh; *(ushort4*)&g_Ql[o] = ql;
        *(ushort4*)&g_Kh[o] = kh; *(ushort4*)&g_Kl[o] = kl;
    }
}

// ---------------- K2m: scores via mma.sync + ldmatrix; E->bf16 split; colsum atomics ----------------
__global__ __launch_bounds__(256) void k2m(const int* __restrict__ adj)
{
    __shared__ uint32_t sAh[128 * 12];
    __shared__ uint32_t sAl[128 * 12];
    __shared__ uint32_t sBh[128 * 12];
    __shared__ uint32_t sBl[128 * 12];

    int tid = threadIdx.x;
    int wid = tid / 32, lane = tid % 32;
    int wm = wid >> 2, wn = wid & 3;
    int g = lane >> 2, q = lane & 3;
    int b = blockIdx.z, mbase = blockIdx.y * 128, nbase = blockIdx.x * 128;

    const uint16_t* pQh = g_Qh + ((size_t)b * Nn + mbase) * Ee;
    const uint16_t* pQl = g_Ql + ((size_t)b * Nn + mbase) * Ee;
    const uint16_t* pKh = g_Kh + ((size_t)b * Nn + nbase) * Ee;
    const uint16_t* pKl = g_Kl + ((size_t)b * Nn + nbase) * Ee;

    uint32_t aAh = smem_u32(sAh), aAl = smem_u32(sAl);
    uint32_t aBh = smem_u32(sBh), aBl = smem_u32(sBl);

    int lrowA = lane & 15;
    int lcolA = (lane & 16) ? 4 : 0;
    int browB = lane & 7;
    int bselB = (lane & 8) ? 4 : 0;
    int bhalfB = (lane & 16) ? 8 : 0;

    float acc[4][4][4];
    #pragma unroll
    for (int i = 0; i < 4; ++i)
        #pragma unroll
        for (int j = 0; j < 4; ++j)
            #pragma unroll
            for (int c = 0; c < 4; ++c) acc[i][j][c] = 0.f;

    #pragma unroll 1
    for (int ks = 0; ks < 16; ++ks) {
        int kbase = ks * 16;
        #pragma unroll
        for (int p = 0; p < 2; ++p) {
            int v = tid + 256 * p;
            int row = v >> 2, qq = v & 3;
            size_t off = (size_t)row * Ee + kbase + qq * 4;
            *(uint2*)&sAh[row*12 + qq*2] = *(const uint2*)(pQh + off);
            *(uint2*)&sAl[row*12 + qq*2] = *(const uint2*)(pQl + off);
            *(uint2*)&sBh[row*12 + qq*2] = *(const uint2*)(pKh + off);
            *(uint2*)&sBl[row*12 + qq*2] = *(const uint2*)(pKl + off);
        }
        __syncthreads();

        uint32_t ah[4][4], al[4][4], bh[4][2], bl[4][2];
        #pragma unroll
        for (int i = 0; i < 4; ++i) {
            uint32_t offA = (uint32_t)(((wm * 64 + i * 16 + lrowA) * 12 + lcolA) * 4);
            ldsm4(ah[i], aAh + offA);
            ldsm4(al[i], aAl + offA);
        }
        #pragma unroll
        for (int jj = 0; jj < 2; ++jj) {
            uint32_t offB = (uint32_t)(((wn * 32 + jj * 16 + bhalfB + browB) * 12 + bselB) * 4);
            uint32_t th[4], tl[4];
            ldsm4(th, aBh + offB);
            ldsm4(tl, aBl + offB);
            bh[2*jj][0] = th[0]; bh[2*jj][1] = th[1]; bh[2*jj+1][0] = th[2]; bh[2*jj+1][1] = th[3];
            bl[2*jj][0] = tl[0]; bl[2*jj][1] = tl[1]; bl[2*jj+1][0] = tl[2]; bl[2*jj+1][1] = tl[3];
        }
        #pragma unroll
        for (int i = 0; i < 4; ++i)
            #pragma unroll
            for (int j = 0; j < 4; ++j) {
                mma16816(acc[i][j], ah[i], bh[j]);
                mma16816(acc[i][j], ah[i], bl[j]);
                mma16816(acc[i][j], al[i], bh[j]);
            }
        __syncthreads();
    }

    float csum[4][2];
    #pragma unroll
    for (int j = 0; j < 4; ++j) { csum[j][0] = 0.f; csum[j][1] = 0.f; }

    #pragma unroll
    for (int i = 0; i < 4; ++i) {
        #pragma unroll
        for (int half = 0; half < 2; ++half) {
            int r = mbase + wm * 64 + i * 16 + g + half * 8;
            const int* adjrow = adj + (size_t)r * Nn;
            size_t erow = ((size_t)b * Nn + r) * Nn;
            #pragma unroll
            for (int j = 0; j < 4; ++j) {
                int cidx = nbase + wn * 32 + j * 8 + q * 2;
                int2 a2 = *(const int2*)(adjrow + cidx);
                float e0 = (a2.x > 0) ? __expf(acc[i][j][half * 2 + 0]) : 0.f;
                float e1 = (a2.y > 0) ? __expf(acc[i][j][half * 2 + 1]) : 0.f;
                uint16_t h0, l0, h1, l1;
                bf16split(e0, h0, l0);
                bf16split(e1, h1, l1);
                *(uint32_t*)&g_Eh[erow + cidx] = (uint32_t)h0 | ((uint32_t)h1 << 16);
                *(uint32_t*)&g_El[erow + cidx] = (uint32_t)l0 | ((uint32_t)l1 << 16);
                csum[j][0] += e0; csum[j][1] += e1;
            }
        }
    }
    #pragma unroll
    for (int j = 0; j < 4; ++j) {
        int cidx = nbase + wn * 32 + j * 8 + q * 2;
        atomicAdd(&g_cs[b * Nn + cidx],     csum[j][0]);
        atomicAdd(&g_cs[b * Nn + cidx + 1], csum[j][1]);
    }
}

// ---------------- K4m: AGG via mma.sync (E @ xn^T), xn computed inline ----------------
__global__ __launch_bounds__(256) void k4m(const float* __restrict__ x)
{
    __shared__ uint16_t sEh[128 * 40];
    __shared__ uint16_t sEl[128 * 40];
    __shared__ uint16_t sXh[64 * 40];
    __shared__ uint16_t sXl[64 * 40];
    __shared__ float rcs[Nn];

    int tid = threadIdx.x;
    int w = tid / 32, lane = tid % 32;
    int b = blockIdx.y, ibase = blockIdx.x * 128;

    for (int j = tid; j < Nn; j += 256) rcs[j] = 1.0f / g_cs[b * Nn + j];
    __syncthreads();

    const uint16_t* pEh = g_Eh + ((size_t)b * Nn + ibase) * Nn;
    const uint16_t* pEl = g_El + ((size_t)b * Nn + ibase) * Nn;
    const float* xb = x + (size_t)b * Ss * Nn;

    uint32_t aEh = smem_u32(sEh), aEl = smem_u32(sEl);
    uint32_t aXh = smem_u32(sXh), aXl = smem_u32(sXl);

    int lrowA = lane & 15;
    int lcolA = (lane & 16) ? 16 : 0;
    int browB = lane & 7;
    int bselB = (lane & 8) ? 16 : 0;
    int bhalfB = (lane & 16) ? 8 : 0;

    float acc[8][4];
    #pragma unroll
    for (int j = 0; j < 8; ++j)
        #pragma unroll
        for (int c = 0; c < 4; ++c) acc[j][c] = 0.f;

    #pragma unroll 1
    for (int jc = 0; jc < 64; ++jc) {
        int j0 = jc * 32;
        {
            int row = tid >> 1, hf = tid & 1;
            const uint16_t* s = pEh + (size_t)row * Nn + j0 + hf * 16;
            uint16_t* d = sEh + row * 40 + hf * 16;
            *(uint4*)d = *(const uint4*)s;
            *(uint4*)(d + 8) = *(const uint4*)(s + 8);
            s = pEl + (size_t)row * Nn + j0 + hf * 16;
            d = sEl + row * 40 + hf * 16;
            *(uint4*)d = *(const uint4*)s;
            *(uint4*)(d + 8) = *(const uint4*)(s + 8);
        }
        {
            int row = tid >> 2, q4 = tid & 3;
            const float* xp = xb + (size_t)row * Nn + j0 + q4 * 8;
            float4 v0 = *(const float4*)xp;
            float4 v1 = *(const float4*)(xp + 4);
            int jb = j0 + q4 * 8;
            float vv[8] = {v0.x * rcs[jb], v0.y * rcs[jb+1], v0.z * rcs[jb+2], v0.w * rcs[jb+3],
                           v1.x * rcs[jb+4], v1.y * rcs[jb+5], v1.z * rcs[jb+6], v1.w * rcs[jb+7]};
            uint16_t hh[8], ll[8];
            #pragma unroll
            for (int e = 0; e < 8; ++e) bf16split(vv[e], hh[e], ll[e]);
            ushort4 ph0 = {hh[0], hh[1], hh[2], hh[3]}, ph1 = {hh[4], hh[5], hh[6], hh[7]};
            ushort4 pl0 = {ll[0], ll[1], ll[2], ll[3]}, pl1 = {ll[4], ll[5], ll[6], ll[7]};
            uint16_t* d = sXh + row * 40 + q4 * 8;
            *(ushort4*)d = ph0; *(ushort4*)(d + 4) = ph1;
            d = sXl + row * 40 + q4 * 8;
            *(ushort4*)d = pl0; *(ushort4*)(d + 4) = pl1;
        }
        __syncthreads();

        #pragma unroll
        for (int s = 0; s < 2; ++s) {
            uint32_t ah[4], al[4];
            uint32_t offA = (uint32_t)((w * 16 + lrowA) * 80 + s * 32 + lcolA);
            ldsm4(ah, aEh + offA);
            ldsm4(al, aEl + offA);
            #pragma unroll
            for (int jj = 0; jj < 4; ++jj) {
                uint32_t offB = (uint32_t)((jj * 16 + bhalfB + browB) * 80 + s * 32 + bselB);
                uint32_t th[4], tl[4];
                ldsm4(th, aXh + offB);
                ldsm4(tl, aXl + offB);
                uint32_t bh0[2] = {th[0], th[1]}, bh1[2] = {th[2], th[3]};
                uint32_t bl0[2] = {tl[0], tl[1]}, bl1[2] = {tl[2], tl[3]};
                mma16816(acc[2*jj],   ah, bh0);
                mma16816(acc[2*jj],   ah, bl0);
                mma16816(acc[2*jj],   al, bh0);
                mma16816(acc[2*jj+1], ah, bh1);
                mma16816(acc[2*jj+1], ah, bl1);
                mma16816(acc[2*jj+1], al, bh1);
            }
        }
        __syncthreads();
    }

    int g = lane >> 2, q = lane & 3;
    int i0 = ibase + w * 16 + g;
    #pragma unroll
    for (int j8 = 0; j8 < 8; ++j8) {
        int t0 = j8 * 8 + q * 2;
        g_AGG[(size_t)t0 * (Bb * Nn) + b * Nn + i0]           = acc[j8][0];
        g_AGG[(size_t)(t0 + 1) * (Bb * Nn) + b * Nn + i0]     = acc[j8][1];
        g_AGG[(size_t)t0 * (Bb * Nn) + b * Nn + i0 + 8]       = acc[j8][2];
        g_AGG[(size_t)(t0 + 1) * (Bb * Nn) + b * Nn + i0 + 8] = acc[j8][3];
    }
}

// ---------------- K5p: persistent recurrence, W via cp.async 3-stage smem pipeline ----------------
__device__ __forceinline__ void load_h(int kstep, int r, int kp, uint32_t* ah, uint32_t* al) {
    int k0 = kstep * 16;
    ah[0] = __ldcg((const uint32_t*)&g_hh[r * Nn + k0 + kp]);
    ah[1] = __ldcg((const uint32_t*)&g_hh[(r + 8) * Nn + k0 + kp]);
    ah[2] = __ldcg((const uint32_t*)&g_hh[r * Nn + k0 + 8 + kp]);
    ah[3] = __ldcg((const uint32_t*)&g_hh[(r + 8) * Nn + k0 + 8 + kp]);
    al[0] = __ldcg((const uint32_t*)&g_hl[r * Nn + k0 + kp]);
    al[1] = __ldcg((const uint32_t*)&g_hl[(r + 8) * Nn + k0 + kp]);
    al[2] = __ldcg((const uint32_t*)&g_hl[r * Nn + k0 + 8 + kp]);
    al[3] = __ldcg((const uint32_t*)&g_hl[(r + 8) * Nn + k0 + 8 + kp]);
}

__global__ __launch_bounds__(256, 2) void k5p(
    const float* __restrict__ bhr, const float* __restrict__ bhz,
    const float* __restrict__ bhn)
{
    // 3-stage W pipeline: [stage][warp][j][lane] uint4 = 48 KB
    __shared__ uint4 sW[3 * 8 * 4 * 32];

    int tid = threadIdx.x;
    int bid = blockIdx.x;
    int nblkI = bid & 7;
    int ksI   = (bid >> 3) % KS3;
    int gate  = bid / (8 * KS3);
    int w = tid / 32, lane = tid % 32;
    int ntbase = nblkI * 32 + w * 4;
    int kb = (ksI * 128) / KS3;
    int ke = ((ksI + 1) * 128) / KS3;
    int r = lane >> 2;
    int kp = (lane & 3) * 2;

    uint32_t sWbase = smem_u32(sW) + (uint32_t)(w * 4 * 32 + lane) * 16;  // + stage*16KB + j*512
    const uint4* gW = g_WF4 + (((size_t)(gate * 256 + ntbase) * 128) + 0) * 32 + lane;
    // per-j source stride = 128*32 uint4; per-kstep stride = 32 uint4.

    int gid = bid * 256 + tid;
    float rb = 0.f, zb = 0.f, nb = 0.f, hloc = 0.f;
    bool own = (gid < Bb * Nn);
    if (own) { int i = gid % Nn; rb = bhr[i]; zb = bhz[i]; nb = bhn[i]; }

    float* Pme = g_part + (size_t)(gate * KS3 + ksI) * (Bb * Nn);
    unsigned target = 0;

    for (int t = 0; t < Ss; ++t) {
        float agg = own ? g_AGG[(size_t)t * (Bb * Nn) + gid] : 0.f;

        float acc[4][4];
        #pragma unroll
        for (int j = 0; j < 4; ++j)
            #pragma unroll
            for (int c = 0; c < 4; ++c) acc[j][c] = 0.f;

        // prologue: stage kb -> slot 0, kb+1 -> slot 1
        #pragma unroll
        for (int j = 0; j < 4; ++j)
            cpasync16(sWbase + 0 * 16384 + j * 512, gW + (size_t)j * 4096 + (size_t)kb * 32);
        asm volatile("cp.async.commit_group;");
        if (kb + 1 < ke) {
            #pragma unroll
            for (int j = 0; j < 4; ++j)
                cpasync16(sWbase + 1 * 16384 + j * 512, gW + (size_t)j * 4096 + (size_t)(kb + 1) * 32);
        }
        asm volatile("cp.async.commit_group;");

        uint32_t ah[4], al[4], ahn[4], aln[4];
        load_h(kb, r, kp, ah, al);

        int slot = 0;
        #pragma unroll 2
        for (int kstep = kb; kstep < ke; ++kstep) {
            // issue stage kstep+2
            if (kstep + 2 < ke) {
                int s2 = slot + 2; if (s2 >= 3) s2 -= 3;
                #pragma unroll
                for (int j = 0; j < 4; ++j)
                    cpasync16(sWbase + s2 * 16384 + j * 512, gW + (size_t)j * 4096 + (size_t)(kstep + 2) * 32);
            }
            asm volatile("cp.async.commit_group;");
            if (kstep + 1 < ke) load_h(kstep + 1, r, kp, ahn, aln);
            asm volatile("cp.async.wait_group 2;");

            #pragma unroll
            for (int j = 0; j < 4; ++j) {
                uint4 Wc = *(uint4*)((char*)sW + (sWbase - smem_u32(sW)) + slot * 16384 + j * 512);
                uint32_t bh[2] = {Wc.x, Wc.y};
                uint32_t bl[2] = {Wc.z, Wc.w};
                mma16816(acc[j], ah, bh);
                mma16816(acc[j], ah, bl);
                mma16816(acc[j], al, bh);
            }
            #pragma unroll
            for (int u = 0; u < 4; ++u) { ah[u] = ahn[u]; al[u] = aln[u]; }
            if (++slot == 3) slot = 0;
        }
        asm volatile("cp.async.wait_group 0;");

        #pragma unroll
        for (int j = 0; j < 4; ++j) {
            int ncol = (ntbase + j) * 8 + kp;
            *(float2*)&Pme[r * Nn + ncol]       = make_float2(acc[j][0], acc[j][1]);
            *(float2*)&Pme[(r + 8) * Nn + ncol] = make_float2(acc[j][2], acc[j][3]);
        }

        target += NPB;
        __syncthreads();
        if (tid == 0) {
            __threadfence();
            atomicAdd(&g_barcnt, 1u);
            while (*(volatile unsigned*)&g_barcnt < target) __nanosleep(64);
        }
        __syncthreads();

        if (own) {
            float rl = rb, zl = zb, nl = nb;
            #pragma unroll
            for (int p = 0; p < KS3; ++p) {
                rl += __ldcg(&g_part[(size_t)(0 * KS3 + p) * (Bb * Nn) + gid]);
                zl += __ldcg(&g_part[(size_t)(1 * KS3 + p) * (Bb * Nn) + gid]);
                nl += __ldcg(&g_part[(size_t)(2 * KS3 + p) * (Bb * Nn) + gid]);
            }
            float rr = 1.f / (1.f + expf(-(agg + rl)));
            float zz = 1.f / (1.f + expf(-(agg + zl)));
            float nn2 = tanhf(agg + rr * nl);
            float hn = (1.f - zz) * nn2 + zz * hloc;
            hloc = hn;
            __nv_bfloat16 hb = __float2bfloat16(hn);
            g_hh[gid] = hb;
            g_hl[gid] = __float2bfloat16(hn - __bfloat162float(hb));
            if (t == Ss - 1) g_h[gid] = hn;
        }

        target += NPB;
        __syncthreads();
        if (tid == 0) {
            __threadfence();
            atomicAdd(&g_barcnt, 1u);
            while (*(volatile unsigned*)&g_barcnt < target) __nanosleep(64);
        }
        __syncthreads();
    }
}

// ---------------- K7: out[b] = h[b,:].Wo + bo ----------------
__global__ void k7_out(const float* __restrict__ Wo, const float* __restrict__ bo,
                       float* __restrict__ out)
{
    __shared__ float red[256];
    int b = blockIdx.x, tid = threadIdx.x;
    float s = 0.f;
    for (int i = tid; i < Nn; i += 256) s += g_h[b * Nn + i] * Wo[i];
    red[tid] = s;
    __syncthreads();
    for (int off = 128; off > 0; off >>= 1) {
        if (tid < off) red[tid] += red[tid + off];
        __syncthreads();
    }
    if (tid == 0) out[b] = red[0] + bo[0];
}

extern "C" void kernel_launch(void* const* d_in, const int* in_sizes, int n_in,
                              void* d_out, int out_size) {
    const float* x   = (const float*)d_in[0];
    const int*   adj = (const int*)  d_in[1];
    const float* Wq  = (const float*)d_in[2];
    const float* bq  = (const float*)d_in[3];
    const float* Wk  = (const float*)d_in[4];
    const float* bk  = (const float*)d_in[5];
    const float* Whr = (const float*)d_in[6];
    const float* bhr = (const float*)d_in[7];
    const float* Whz = (const float*)d_in[8];
    const float* bhz = (const float*)d_in[9];
    const float* Whn = (const float*)d_in[10];
    const float* bhn = (const float*)d_in[11];
    const float* Wo  = (const float*)d_in[12];
    const float* bo  = (const float*)d_in[13];
    float* out = (float*)d_out;

    kA<<<A_W, 256>>>(x, Wq, bq, Wk, bk, Whr, Whz, Whn);
    k2m<<<dim3(Nn / 128, Nn / 128, Bb), 256>>>(adj);
    k4m<<<dim3(Nn / 128, Bb), 256>>>(x);
    k5p<<<NPB, 256>>>(bhr, bhz, bhn);
    k7_out<<<Bb, 256>>>(Wo, bo, out);
}

// round 16
// speedup vs baseline: 1.5553x; 1.5553x over previous
#include <cuda_runtime.h>
#include <cuda_bf16.h>
#include <cstdint>

constexpr int Bb = 16, Ss = 64, Nn = 2048, Ee = 256;
constexpr int KS3 = 12;    // k-ranges for recurrence MMA
constexpr int NPB = 288;   // persistent blocks (3 gates x 8 nblk x 12 ks) = 144*2

// ---------------- scratch ----------------
__device__ uint16_t g_Eh[(size_t)Bb * Nn * Nn];
__device__ uint16_t g_El[(size_t)Bb * Nn * Nn];
__device__ float g_cs[Bb * Nn];
__device__ float g_AGG[Ss * Bb * Nn];
__device__ float g_part[3 * KS3 * Bb * Nn];
__device__ float g_h[Bb * Nn];
__device__ uint16_t g_Qh[(size_t)Bb * Nn * Ee];
__device__ uint16_t g_Ql[(size_t)Bb * Nn * Ee];
__device__ uint16_t g_Kh[(size_t)Bb * Nn * Ee];
__device__ uint16_t g_Kl[(size_t)Bb * Nn * Ee];
// W gate weights, fragment order, hi/lo interleaved per lane:
// [gate][ntile(256)][kstep(128)][lane(32)] -> uint4 {hi_reg0, hi_reg1, lo_reg0, lo_reg1}
__device__ uint4 g_WF4[3u * 256 * 128 * 32];
__device__ __nv_bfloat16 g_hh[Bb * Nn];
__device__ __nv_bfloat16 g_hl[Bb * Nn];
__device__ unsigned g_barcnt;

__device__ __forceinline__ void bf16split(float f, uint16_t& h, uint16_t& l) {
    __nv_bfloat16 hb = __float2bfloat16(f);
    __nv_bfloat16 lb = __float2bfloat16(f - __bfloat162float(hb));
    h = *(uint16_t*)&hb; l = *(uint16_t*)&lb;
}
__device__ __forceinline__ void mma16816(float* c, const uint32_t* a, const uint32_t* bfr) {
    asm volatile(
        "mma.sync.aligned.m16n8k16.row.col.f32.bf16.bf16.f32 "
        "{%0,%1,%2,%3}, {%4,%5,%6,%7}, {%8,%9}, {%0,%1,%2,%3};"
        : "+f"(c[0]), "+f"(c[1]), "+f"(c[2]), "+f"(c[3])
        : "r"(a[0]), "r"(a[1]), "r"(a[2]), "r"(a[3]), "r"(bfr[0]), "r"(bfr[1]));
}
__device__ __forceinline__ uint32_t smem_u32(const void* p) {
    uint32_t a;
    asm("{ .reg .u64 t; cvta.to.shared.u64 t, %1; cvt.u32.u64 %0, t; }" : "=r"(a) : "l"(p));
    return a;
}
__device__ __forceinline__ void ldsm4(uint32_t* d, uint32_t addr) {
    asm volatile("ldmatrix.sync.aligned.m8n8.x4.shared.b16 {%0,%1,%2,%3}, [%4];"
        : "=r"(d[0]), "=r"(d[1]), "=r"(d[2]), "=r"(d[3]) : "r"(addr));
}

// ======== Fused setup kernel: [0,1024)=k1 proj, [1024,1152)=zero, [1152,+12288)=W split ========
constexpr int A_K1 = 1024, A_Z = A_K1 + 128, A_W = A_Z + 12288;

__global__ __launch_bounds__(256) void kA(
    const float* __restrict__ x,
    const float* __restrict__ Wq, const float* __restrict__ bq,
    const float* __restrict__ Wk, const float* __restrict__ bk,
    const float* __restrict__ Whr, const float* __restrict__ Whz,
    const float* __restrict__ Whn)
{
    int bid = blockIdx.x;
    int tid = threadIdx.x;

    if (bid >= A_Z) {
        long long t = (long long)(bid - A_Z) * 256 + tid;
        int gate = (int)(t / (Nn * 512));
        int rem  = (int)(t % (Nn * 512));
        int n = rem / 512;
        int s = rem % 512;
        int kstep = s >> 2, q = s & 3;
        int k0 = kstep * 16 + q * 2;
        const float* W = (gate == 0) ? Whr : ((gate == 1) ? Whz : Whn);
        float w0 = W[(size_t)n * Nn + k0];
        float w1 = W[(size_t)n * Nn + k0 + 1];
        float w2 = W[(size_t)n * Nn + k0 + 8];
        float w3 = W[(size_t)n * Nn + k0 + 9];
        uint16_t h0, l0, h1, l1, h2, l2, h3, l3;
        bf16split(w0, h0, l0); bf16split(w1, h1, l1);
        bf16split(w2, h2, l2); bf16split(w3, h3, l3);
        uint4 v;
        v.x = (uint32_t)h0 | ((uint32_t)h1 << 16);
        v.y = (uint32_t)h2 | ((uint32_t)h3 << 16);
        v.z = (uint32_t)l0 | ((uint32_t)l1 << 16);
        v.w = (uint32_t)l2 | ((uint32_t)l3 << 16);
        int lane = (n & 7) * 4 + q;
        uint32_t idx = (((uint32_t)gate * 256 + (n >> 3)) * 128 + kstep) * 32 + lane;
        g_WF4[idx] = v;
        return;
    }
    if (bid >= A_K1) {
        int idx = (bid - A_K1) * 256 + tid;
        if (idx == 0) g_barcnt = 0u;
        if (idx < Bb * Nn) {
            g_cs[idx] = 0.f; g_h[idx] = 0.f;
            g_hh[idx] = __float2bfloat16(0.f);
            g_hl[idx] = __float2bfloat16(0.f);
        }
        return;
    }

    // ---- Q,K projection -> bf16 hi/lo ----
    __shared__ float As[16][132];
    __shared__ float wqs[64][16];
    __shared__ float wks[64][16];
    int bx = bid & 15, by = (bid >> 4) & 3, bz = bid >> 6;
    int b = bz, nbase = bx * 128, ebase = by * 64;
    int tn = tid % 16, te = tid / 16;

    float4 accq[8], acck[8];
    #pragma unroll
    for (int i = 0; i < 8; ++i) { accq[i] = make_float4(0,0,0,0); acck[i] = make_float4(0,0,0,0); }

    for (int kc = 0; kc < 4; ++kc) {
        int kbase = kc * 16;
        #pragma unroll
        for (int p = 0; p < 2; ++p) {
            int v = tid + 256 * p;
            int k = v / 32, mq = v % 32;
            *(float4*)&As[k][mq * 4] =
                *(const float4*)&x[((size_t)(b * Ss + kbase + k)) * Nn + nbase + mq * 4];
        }
        {
            int e = tid / 4, kq = tid % 4;
            *(float4*)&wqs[e][kq * 4] = *(const float4*)&Wq[(ebase + e) * Ss + kbase + kq * 4];
            *(float4*)&wks[e][kq * 4] = *(const float4*)&Wk[(ebase + e) * Ss + kbase + kq * 4];
        }
        __syncthreads();
        #pragma unroll
        for (int kk = 0; kk < 16; ++kk) {
            float4 alo = *(float4*)&As[kk][tn * 8];
            float4 ahi = *(float4*)&As[kk][tn * 8 + 4];
            float av[8] = {alo.x, alo.y, alo.z, alo.w, ahi.x, ahi.y, ahi.z, ahi.w};
            float wq0 = wqs[te*4+0][kk], wq1 = wqs[te*4+1][kk];
            float wq2 = wqs[te*4+2][kk], wq3 = wqs[te*4+3][kk];
            float wk0 = wks[te*4+0][kk], wk1 = wks[te*4+1][kk];
            float wk2 = wks[te*4+2][kk], wk3 = wks[te*4+3][kk];
            #pragma unroll
            for (int i = 0; i < 8; ++i) {
                accq[i].x += av[i]*wq0; accq[i].y += av[i]*wq1;
                accq[i].z += av[i]*wq2; accq[i].w += av[i]*wq3;
                acck[i].x += av[i]*wk0; acck[i].y += av[i]*wk1;
                acck[i].z += av[i]*wk2; acck[i].w += av[i]*wk3;
            }
        }
        __syncthreads();
    }
    float4 bq4 = *(const float4*)&bq[ebase + te * 4];
    float4 bk4 = *(const float4*)&bk[ebase + te * 4];
    #pragma unroll
    for (int i = 0; i < 8; ++i) {
        int n = nbase + tn * 8 + i;
        size_t o = ((size_t)b * Nn + n) * Ee + ebase + te * 4;
        float qa[4] = {accq[i].x + bq4.x, accq[i].y + bq4.y, accq[i].z + bq4.z, accq[i].w + bq4.w};
        float ka[4] = {acck[i].x + bk4.x, acck[i].y + bk4.y, acck[i].z + bk4.z, acck[i].w + bk4.w};
        ushort4 qh, ql, kh, kl;
        bf16split(qa[0], qh.x, ql.x); bf16split(qa[1], qh.y, ql.y);
        bf16split(qa[2], qh.z, ql.z); bf16split(qa[3], qh.w, ql.w);
        bf16split(ka[0], kh.x, kl.x); bf16split(ka[1], kh.y, kl.y);
        bf16split(ka[2], kh.z, kl.z); bf16split(ka[3], kh.w, kl.w);
        *(ushort4*)&g_Qh[o] = qh; *(ushort4*)&g_Ql[o] = ql;
        *(ushort4*)&g_Kh[o] = kh; *(ushort4*)&g_Kl[o] = kl;
    }
}

// ---------------- K2m: scores via mma.sync + ldmatrix, 32-k chunks, 80B-stride smem ----------------
__global__ __launch_bounds__(256) void k2m(const int* __restrict__ adj)
{
    __shared__ uint16_t sAh[128 * 40];
    __shared__ uint16_t sAl[128 * 40];
    __shared__ uint16_t sBh[128 * 40];
    __shared__ uint16_t sBl[128 * 40];

    int tid = threadIdx.x;
    int wid = tid / 32, lane = tid % 32;
    int wm = wid >> 2, wn = wid & 3;
    int g = lane >> 2, q = lane & 3;
    int b = blockIdx.z, mbase = blockIdx.y * 128, nbase = blockIdx.x * 128;

    const uint16_t* pQh = g_Qh + ((size_t)b * Nn + mbase) * Ee;
    const uint16_t* pQl = g_Ql + ((size_t)b * Nn + mbase) * Ee;
    const uint16_t* pKh = g_Kh + ((size_t)b * Nn + nbase) * Ee;
    const uint16_t* pKl = g_Kl + ((size_t)b * Nn + nbase) * Ee;

    uint32_t aAh = smem_u32(sAh), aAl = smem_u32(sAl);
    uint32_t aBh = smem_u32(sBh), aBl = smem_u32(sBl);

    int lrowA = lane & 15;
    int lcolA = (lane & 16) ? 16 : 0;   // bytes within 32B k-chunk
    int browB = lane & 7;
    int bselB = (lane & 8) ? 16 : 0;
    int bhalfB = (lane & 16) ? 8 : 0;

    float acc[4][4][4];
    #pragma unroll
    for (int i = 0; i < 4; ++i)
        #pragma unroll
        for (int j = 0; j < 4; ++j)
            #pragma unroll
            for (int c = 0; c < 4; ++c) acc[i][j][c] = 0.f;

    #pragma unroll 1
    for (int kc = 0; kc < 8; ++kc) {
        int k0 = kc * 32;
        {   // stage 128 rows x 32 k-elems (64B) per array, uint4 loads
            int row = tid >> 1, hf = tid & 1;
            size_t off = (size_t)row * Ee + k0 + hf * 16;
            uint16_t* d;
            d = sAh + row * 40 + hf * 16;
            *(uint4*)d = *(const uint4*)(pQh + off);
            *(uint4*)(d + 8) = *(const uint4*)(pQh + off + 8);
            d = sAl + row * 40 + hf * 16;
            *(uint4*)d = *(const uint4*)(pQl + off);
            *(uint4*)(d + 8) = *(const uint4*)(pQl + off + 8);
            d = sBh + row * 40 + hf * 16;
            *(uint4*)d = *(const uint4*)(pKh + off);
            *(uint4*)(d + 8) = *(const uint4*)(pKh + off + 8);
            d = sBl + row * 40 + hf * 16;
            *(uint4*)d = *(const uint4*)(pKl + off);
            *(uint4*)(d + 8) = *(const uint4*)(pKl + off + 8);
        }
        __syncthreads();

        #pragma unroll
        for (int s = 0; s < 2; ++s) {
            uint32_t ah[4][4], al[4][4], bh[4][2], bl[4][2];
            #pragma unroll
            for (int i = 0; i < 4; ++i) {
                uint32_t offA = (uint32_t)((wm * 64 + i * 16 + lrowA) * 80 + s * 32 + lcolA);
                ldsm4(ah[i], aAh + offA);
                ldsm4(al[i], aAl + offA);
            }
            #pragma unroll
            for (int jj = 0; jj < 2; ++jj) {
                uint32_t offB = (uint32_t)((wn * 32 + jj * 16 + bhalfB + browB) * 80 + s * 32 + bselB);
                uint32_t th[4], tl[4];
                ldsm4(th, aBh + offB);
                ldsm4(tl, aBl + offB);
                bh[2*jj][0] = th[0]; bh[2*jj][1] = th[1]; bh[2*jj+1][0] = th[2]; bh[2*jj+1][1] = th[3];
                bl[2*jj][0] = tl[0]; bl[2*jj][1] = tl[1]; bl[2*jj+1][0] = tl[2]; bl[2*jj+1][1] = tl[3];
            }
            #pragma unroll
            for (int i = 0; i < 4; ++i)
                #pragma unroll
                for (int j = 0; j < 4; ++j) {
                    mma16816(acc[i][j], ah[i], bh[j]);
                    mma16816(acc[i][j], ah[i], bl[j]);
                    mma16816(acc[i][j], al[i], bh[j]);
                }
        }
        __syncthreads();
    }

    float csum[4][2];
    #pragma unroll
    for (int j = 0; j < 4; ++j) { csum[j][0] = 0.f; csum[j][1] = 0.f; }

    #pragma unroll
    for (int i = 0; i < 4; ++i) {
        #pragma unroll
        for (int half = 0; half < 2; ++half) {
            int r = mbase + wm * 64 + i * 16 + g + half * 8;
            const int* adjrow = adj + (size_t)r * Nn;
            size_t erow = ((size_t)b * Nn + r) * Nn;
            #pragma unroll
            for (int j = 0; j < 4; ++j) {
                int cidx = nbase + wn * 32 + j * 8 + q * 2;
                int2 a2 = *(const int2*)(adjrow + cidx);
                float e0 = (a2.x > 0) ? __expf(acc[i][j][half * 2 + 0]) : 0.f;
                float e1 = (a2.y > 0) ? __expf(acc[i][j][half * 2 + 1]) : 0.f;
                uint16_t h0, l0, h1, l1;
                bf16split(e0, h0, l0);
                bf16split(e1, h1, l1);
                *(uint32_t*)&g_Eh[erow + cidx] = (uint32_t)h0 | ((uint32_t)h1 << 16);
                *(uint32_t*)&g_El[erow + cidx] = (uint32_t)l0 | ((uint32_t)l1 << 16);
                csum[j][0] += e0; csum[j][1] += e1;
            }
        }
    }
    #pragma unroll
    for (int j = 0; j < 4; ++j) {
        int cidx = nbase + wn * 32 + j * 8 + q * 2;
        atomicAdd(&g_cs[b * Nn + cidx],     csum[j][0]);
        atomicAdd(&g_cs[b * Nn + cidx + 1], csum[j][1]);
    }
}

// ---------------- K4m: AGG via mma.sync (E @ xn^T), xn computed inline ----------------
__global__ __launch_bounds__(256) void k4m(const float* __restrict__ x)
{
    __shared__ uint16_t sEh[128 * 40];
    __shared__ uint16_t sEl[128 * 40];
    __shared__ uint16_t sXh[64 * 40];
    __shared__ uint16_t sXl[64 * 40];
    __shared__ float rcs[Nn];

    int tid = threadIdx.x;
    int w = tid / 32, lane = tid % 32;
    int b = blockIdx.y, ibase = blockIdx.x * 128;

    for (int j = tid; j < Nn; j += 256) rcs[j] = 1.0f / g_cs[b * Nn + j];
    __syncthreads();

    const uint16_t* pEh = g_Eh + ((size_t)b * Nn + ibase) * Nn;
    const uint16_t* pEl = g_El + ((size_t)b * Nn + ibase) * Nn;
    const float* xb = x + (size_t)b * Ss * Nn;

    uint32_t aEh = smem_u32(sEh), aEl = smem_u32(sEl);
    uint32_t aXh = smem_u32(sXh), aXl = smem_u32(sXl);

    int lrowA = lane & 15;
    int lcolA = (lane & 16) ? 16 : 0;
    int browB = lane & 7;
    int bselB = (lane & 8) ? 16 : 0;
    int bhalfB = (lane & 16) ? 8 : 0;

    float acc[8][4];
    #pragma unroll
    for (int j = 0; j < 8; ++j)
        #pragma unroll
        for (int c = 0; c < 4; ++c) acc[j][c] = 0.f;

    #pragma unroll 1
    for (int jc = 0; jc < 64; ++jc) {
        int j0 = jc * 32;
        {
            int row = tid >> 1, hf = tid & 1;
            const uint16_t* s = pEh + (size_t)row * Nn + j0 + hf * 16;
            uint16_t* d = sEh + row * 40 + hf * 16;
            *(uint4*)d = *(const uint4*)s;
            *(uint4*)(d + 8) = *(const uint4*)(s + 8);
            s = pEl + (size_t)row * Nn + j0 + hf * 16;
            d = sEl + row * 40 + hf * 16;
            *(uint4*)d = *(const uint4*)s;
            *(uint4*)(d + 8) = *(const uint4*)(s + 8);
        }
        {
            int row = tid >> 2, q4 = tid & 3;
            const float* xp = xb + (size_t)row * Nn + j0 + q4 * 8;
            float4 v0 = *(const float4*)xp;
            float4 v1 = *(const float4*)(xp + 4);
            int jb = j0 + q4 * 8;
            float vv[8] = {v0.x * rcs[jb], v0.y * rcs[jb+1], v0.z * rcs[jb+2], v0.w * rcs[jb+3],
                           v1.x * rcs[jb+4], v1.y * rcs[jb+5], v1.z * rcs[jb+6], v1.w * rcs[jb+7]};
            uint16_t hh[8], ll[8];
            #pragma unroll
            for (int e = 0; e < 8; ++e) bf16split(vv[e], hh[e], ll[e]);
            ushort4 ph0 = {hh[0], hh[1], hh[2], hh[3]}, ph1 = {hh[4], hh[5], hh[6], hh[7]};
            ushort4 pl0 = {ll[0], ll[1], ll[2], ll[3]}, pl1 = {ll[4], ll[5], ll[6], ll[7]};
            uint16_t* d = sXh + row * 40 + q4 * 8;
            *(ushort4*)d = ph0; *(ushort4*)(d + 4) = ph1;
            d = sXl + row * 40 + q4 * 8;
            *(ushort4*)d = pl0; *(ushort4*)(d + 4) = pl1;
        }
        __syncthreads();

        #pragma unroll
        for (int s = 0; s < 2; ++s) {
            uint32_t ah[4], al[4];
            uint32_t offA = (uint32_t)((w * 16 + lrowA) * 80 + s * 32 + lcolA);
            ldsm4(ah, aEh + offA);
            ldsm4(al, aEl + offA);
            #pragma unroll
            for (int jj = 0; jj < 4; ++jj) {
                uint32_t offB = (uint32_t)((jj * 16 + bhalfB + browB) * 80 + s * 32 + bselB);
                uint32_t th[4], tl[4];
                ldsm4(th, aXh + offB);
                ldsm4(tl, aXl + offB);
                uint32_t bh0[2] = {th[0], th[1]}, bh1[2] = {th[2], th[3]};
                uint32_t bl0[2] = {tl[0], tl[1]}, bl1[2] = {tl[2], tl[3]};
                mma16816(acc[2*jj],   ah, bh0);
                mma16816(acc[2*jj],   ah, bl0);
                mma16816(acc[2*jj],   al, bh0);
                mma16816(acc[2*jj+1], ah, bh1);
                mma16816(acc[2*jj+1], ah, bl1);
                mma16816(acc[2*jj+1], al, bh1);
            }
        }
        __syncthreads();
    }

    int g = lane >> 2, q = lane & 3;
    int i0 = ibase + w * 16 + g;
    #pragma unroll
    for (int j8 = 0; j8 < 8; ++j8) {
        int t0 = j8 * 8 + q * 2;
        g_AGG[(size_t)t0 * (Bb * Nn) + b * Nn + i0]           = acc[j8][0];
        g_AGG[(size_t)(t0 + 1) * (Bb * Nn) + b * Nn + i0]     = acc[j8][1];
        g_AGG[(size_t)t0 * (Bb * Nn) + b * Nn + i0 + 8]       = acc[j8][2];
        g_AGG[(size_t)(t0 + 1) * (Bb * Nn) + b * Nn + i0 + 8] = acc[j8][3];
    }
}

// ---------------- K5p: persistent recurrence, W double-buffered uint4 loads (R14) ----------------
__device__ __forceinline__ void load_h(int kstep, int r, int kp, uint32_t* ah, uint32_t* al) {
    int k0 = kstep * 16;
    ah[0] = __ldcg((const uint32_t*)&g_hh[r * Nn + k0 + kp]);
    ah[1] = __ldcg((const uint32_t*)&g_hh[(r + 8) * Nn + k0 + kp]);
    ah[2] = __ldcg((const uint32_t*)&g_hh[r * Nn + k0 + 8 + kp]);
    ah[3] = __ldcg((const uint32_t*)&g_hh[(r + 8) * Nn + k0 + 8 + kp]);
    al[0] = __ldcg((const uint32_t*)&g_hl[r * Nn + k0 + kp]);
    al[1] = __ldcg((const uint32_t*)&g_hl[(r + 8) * Nn + k0 + kp]);
    al[2] = __ldcg((const uint32_t*)&g_hl[r * Nn + k0 + 8 + kp]);
    al[3] = __ldcg((const uint32_t*)&g_hl[(r + 8) * Nn + k0 + 8 + kp]);
}
__device__ __forceinline__ void load_w(int gate, int ntbase, int kstep, int lane, uint4* Wf) {
    #pragma unroll
    for (int j = 0; j < 4; ++j) {
        size_t idx = (((size_t)(gate * 256 + ntbase + j) * 128 + kstep) * 32 + lane);
        Wf[j] = __ldcg(&g_WF4[idx]);
    }
}

__global__ __launch_bounds__(256, 2) void k5p(
    const float* __restrict__ bhr, const float* __restrict__ bhz,
    const float* __restrict__ bhn)
{
    int tid = threadIdx.x;
    int bid = blockIdx.x;
    int nblkI = bid & 7;
    int ksI   = (bid >> 3) % KS3;
    int gate  = bid / (8 * KS3);
    int w = tid / 32, lane = tid % 32;
    int ntbase = nblkI * 32 + w * 4;
    int kb = (ksI * 128) / KS3;
    int ke = ((ksI + 1) * 128) / KS3;
    int r = lane >> 2;
    int kp = (lane & 3) * 2;

    int gid = bid * 256 + tid;
    float rb = 0.f, zb = 0.f, nb = 0.f, hloc = 0.f;
    bool own = (gid < Bb * Nn);
    if (own) { int i = gid % Nn; rb = bhr[i]; zb = bhz[i]; nb = bhn[i]; }

    float* Pme = g_part + (size_t)(gate * KS3 + ksI) * (Bb * Nn);
    unsigned target = 0;

    for (int t = 0; t < Ss; ++t) {
        float agg = own ? g_AGG[(size_t)t * (Bb * Nn) + gid] : 0.f;

        float acc[4][4];
        #pragma unroll
        for (int j = 0; j < 4; ++j)
            #pragma unroll
            for (int c = 0; c < 4; ++c) acc[j][c] = 0.f;

        uint32_t ah[4], al[4], ahn[4], aln[4];
        uint4 Wc[4], Wn[4];
        load_h(kb, r, kp, ah, al);
        load_w(gate, ntbase, kb, lane, Wc);
        #pragma unroll 2
        for (int kstep = kb; kstep < ke; ++kstep) {
            if (kstep + 1 < ke) {
                load_h(kstep + 1, r, kp, ahn, aln);
                load_w(gate, ntbase, kstep + 1, lane, Wn);
            }
            #pragma unroll
            for (int j = 0; j < 4; ++j) {
                uint32_t bh[2] = {Wc[j].x, Wc[j].y};
                uint32_t bl[2] = {Wc[j].z, Wc[j].w};
                mma16816(acc[j], ah, bh);
                mma16816(acc[j], ah, bl);
                mma16816(acc[j], al, bh);
            }
            #pragma unroll
            for (int u = 0; u < 4; ++u) { ah[u] = ahn[u]; al[u] = aln[u]; Wc[u] = Wn[u]; }
        }
        #pragma unroll
        for (int j = 0; j < 4; ++j) {
            int ncol = (ntbase + j) * 8 + kp;
            *(float2*)&Pme[r * Nn + ncol]       = make_float2(acc[j][0], acc[j][1]);
            *(float2*)&Pme[(r + 8) * Nn + ncol] = make_float2(acc[j][2], acc[j][3]);
        }

        target += NPB;
        __syncthreads();
        if (tid == 0) {
            __threadfence();
            atomicAdd(&g_barcnt, 1u);
            while (*(volatile unsigned*)&g_barcnt < target) __nanosleep(64);
        }
        __syncthreads();

        if (own) {
            float rl = rb, zl = zb, nl = nb;
            #pragma unroll
            for (int p = 0; p < KS3; ++p) {
                rl += __ldcg(&g_part[(size_t)(0 * KS3 + p) * (Bb * Nn) + gid]);
                zl += __ldcg(&g_part[(size_t)(1 * KS3 + p) * (Bb * Nn) + gid]);
                nl += __ldcg(&g_part[(size_t)(2 * KS3 + p) * (Bb * Nn) + gid]);
            }
            float rr = 1.f / (1.f + expf(-(agg + rl)));
            float zz = 1.f / (1.f + expf(-(agg + zl)));
            float nn2 = tanhf(agg + rr * nl);
            float hn = (1.f - zz) * nn2 + zz * hloc;
            hloc = hn;
            __nv_bfloat16 hb = __float2bfloat16(hn);
            g_hh[gid] = hb;
            g_hl[gid] = __float2bfloat16(hn - __bfloat162float(hb));
            if (t == Ss - 1) g_h[gid] = hn;
        }

        target += NPB;
        __syncthreads();
        if (tid == 0) {
            __threadfence();
            atomicAdd(&g_barcnt, 1u);
            while (*(volatile unsigned*)&g_barcnt < target) __nanosleep(64);
        }
        __syncthreads();
    }
}

// ---------------- K7: out[b] = h[b,:].Wo + bo ----------------
__global__ void k7_out(const float* __restrict__ Wo, const float* __restrict__ bo,
                       float* __restrict__ out)
{
    __shared__ float red[256];
    int b = blockIdx.x, tid = threadIdx.x;
    float s = 0.f;
    for (int i = tid; i < Nn; i += 256) s += g_h[b * Nn + i] * Wo[i];
    red[tid] = s;
    __syncthreads();
    for (int off = 128; off > 0; off >>= 1) {
        if (tid < off) red[tid] += red[tid + off];
        __syncthreads();
    }
    if (tid == 0) out[b] = red[0] + bo[0];
}

extern "C" void kernel_launch(void* const* d_in, const int* in_sizes, int n_in,
                              void* d_out, int out_size) {
    const float* x   = (const float*)d_in[0];
    const int*   adj = (const int*)  d_in[1];
    const float* Wq  = (const float*)d_in[2];
    const float* bq  = (const float*)d_in[3];
    const float* Wk  = (const float*)d_in[4];
    const float* bk  = (const float*)d_in[5];
    const float* Whr = (const float*)d_in[6];
    const float* bhr = (const float*)d_in[7];
    const float* Whz = (const float*)d_in[8];
    const float* bhz = (const float*)d_in[9];
    const float* Whn = (const float*)d_in[10];
    const float* bhn = (const float*)d_in[11];
    const float* Wo  = (const float*)d_in[12];
    const float* bo  = (const float*)d_in[13];
    float* out = (float*)d_out;

    kA<<<A_W, 256>>>(x, Wq, bq, Wk, bk, Whr, Whz, Whn);
    k2m<<<dim3(Nn / 128, Nn / 128, Bb), 256>>>(adj);
    k4m<<<dim3(Nn / 128, Bb), 256>>>(x);
    k5p<<<NPB, 256>>>(bhr, bhz, bhn);
    k7_out<<<Bb, 256>>>(Wo, bo, out);
}